// round 3
// baseline (speedup 1.0000x reference)
#include <cuda_runtime.h>
#include <math.h>

#define B_    32
#define T_    10
#define N_    1000
#define C_    96
#define E_    8000
#define G_    (B_*T_)      // 320
#define ETOT  (E_+N_)      // 9000 edges incl self loops
#define C4_   (C_/4)       // 24

// ---- device scratch (no allocations allowed) ----
__device__ float4 g_params[C_];            // (Wl[c], Wr[c], 0.4*att[c], bl[c]+br[c])
__device__ float  g_scal[3];               // 0.6*<att,Wl>, 0.6*<att,Wr>, 0.6*<att,bl+br>
__device__ float4 g_add4[T_*C4_];          // bl+bias+pos, per (t,c)
__device__ int    g_deg[N_];
__device__ int    g_cnt[N_];
__device__ int    g_off[N_+1];
__device__ int    g_tmp[ETOT];             // edge ids, bucketed (unsorted)
__device__ int    g_src[ETOT];
__device__ int    g_dst[ETOT];
__device__ float  g_e[G_*ETOT];            // 11.52 MB logits
__device__ float  g_S[G_*N_];              // per-node softmax-weighted source mean

// ---------------------------------------------------------------------------
// Setup: params pack, scalar dots, bias+pos table, zero counters
// ---------------------------------------------------------------------------
__global__ void k_setup(const float* __restrict__ Wl, const float* __restrict__ bl,
                        const float* __restrict__ Wr, const float* __restrict__ br,
                        const float* __restrict__ att, const float* __restrict__ bias) {
    __shared__ float sred[32];
    int tid  = threadIdx.x;
    int lane = tid & 31;
    int wid  = tid >> 5;

    if (tid < N_) { g_deg[tid] = 0; g_cnt[tid] = 0; }

    float d0 = 0.f, d1 = 0.f, d2 = 0.f;
    if (tid < C_) {
        float wl = Wl[tid], wr = Wr[tid], a = att[tid], k = bl[tid] + br[tid];
        g_params[tid] = make_float4(wl, wr, 0.4f * a, k);
        d0 = a * wl; d1 = a * wr; d2 = a * k;

        // positional embedding + bias table
        int   pair = tid >> 1;
        float freq = __expf(-(float)(2 * pair) * (logf(10000.f) / (float)C_));
        float badd = bl[tid] + bias[tid];
        float* addf = (float*)g_add4;
        for (int t = 0; t < T_; t++) {
            float arg = (float)t * freq;
            addf[t * C_ + tid] = badd + ((tid & 1) ? cosf(arg) : sinf(arg));
        }
    }

    // block reduce the three dots (blockDim = 1024 -> 32 warps)
    float vals[3] = {d0, d1, d2};
    for (int r = 0; r < 3; r++) {
        float v = vals[r];
        #pragma unroll
        for (int o = 16; o; o >>= 1) v += __shfl_down_sync(0xffffffffu, v, o);
        if (lane == 0) sred[wid] = v;
        __syncthreads();
        if (wid == 0) {
            float w = sred[lane];
            #pragma unroll
            for (int o = 16; o; o >>= 1) w += __shfl_down_sync(0xffffffffu, w, o);
            if (lane == 0) g_scal[r] = 0.6f * w;
        }
        __syncthreads();
    }
}

// ---------------------------------------------------------------------------
// CSR build: histogram -> scan -> atomic bucket scatter -> per-node sort by
// edge id (unique key => deterministic CSR regardless of atomic order)
// ---------------------------------------------------------------------------
__device__ __forceinline__ int edge_dst(const int* EI, int e) {
    return (e < E_) ? EI[E_ + e] : (e - E_);
}
__device__ __forceinline__ int edge_src(const int* EI, int e) {
    return (e < E_) ? EI[e] : (e - E_);
}

__global__ void k_hist(const int* __restrict__ EI) {
    int e = blockIdx.x * blockDim.x + threadIdx.x;
    if (e >= ETOT) return;
    atomicAdd(&g_deg[edge_dst(EI, e)], 1);
}

__global__ void k_scan() {
    __shared__ int s[1024];
    int tid = threadIdx.x;
    s[tid] = (tid < N_) ? g_deg[tid] : 0;
    __syncthreads();
    for (int o = 1; o < 1024; o <<= 1) {
        int t = (tid >= o) ? s[tid - o] : 0;
        __syncthreads();
        s[tid] += t;
        __syncthreads();
    }
    if (tid == 0) g_off[0] = 0;
    if (tid < N_) g_off[tid + 1] = s[tid];
}

__global__ void k_scatter(const int* __restrict__ EI) {
    int e = blockIdx.x * blockDim.x + threadIdx.x;
    if (e >= ETOT) return;
    int d = edge_dst(EI, e);
    int slot = g_off[d] + atomicAdd(&g_cnt[d], 1);
    g_tmp[slot] = e;
}

// thread per node: insertion-sort its bucket by edge id, emit src/dst arrays
__global__ void k_sort(const int* __restrict__ EI) {
    int i = blockIdx.x * blockDim.x + threadIdx.x;
    if (i >= N_) return;
    int lo = g_off[i], hi = g_off[i + 1];
    for (int a = lo + 1; a < hi; a++) {
        int key = g_tmp[a];
        int b = a - 1;
        while (b >= lo && g_tmp[b] > key) { g_tmp[b + 1] = g_tmp[b]; b--; }
        g_tmp[b + 1] = key;
    }
    for (int a = lo; a < hi; a++) {
        g_src[a] = edge_src(EI, g_tmp[a]);
        g_dst[a] = i;
    }
}

// ---------------------------------------------------------------------------
// Logits: e = S0*xj + S1*xi + S2 + sum_c 0.4*att[c]*|xj*Wl[c] + xi*Wr[c] + K[c]|
// one thread per (graph, csr slot)
// ---------------------------------------------------------------------------
__global__ void k_logits(const float* __restrict__ x) {
    __shared__ float4 P[C_];
    __shared__ float  Ssc[3];
    int tl = threadIdx.x;
    if (tl < C_) P[tl] = g_params[tl];
    if (tl < 3)  Ssc[tl] = g_scal[tl];
    __syncthreads();

    int tid = blockIdx.x * blockDim.x + tl;
    if (tid >= G_ * ETOT) return;
    int g = tid / ETOT;
    int s = tid - g * ETOT;

    const float* xg = x + g * N_;
    float xj = __ldg(&xg[g_src[s]]);
    float xi = __ldg(&xg[g_dst[s]]);

    float acc = fmaf(Ssc[0], xj, fmaf(Ssc[1], xi, Ssc[2]));
    #pragma unroll
    for (int c = 0; c < C_; c++) {
        float4 p = P[c];
        float  z = fmaf(xj, p.x, fmaf(xi, p.y, p.w));
        acc = fmaf(p.z, fabsf(z), acc);
    }
    g_e[tid] = acc;
}

// ---------------------------------------------------------------------------
// Per-node online softmax over incoming edges -> S[g,i] = sum alpha * x[src]
// ---------------------------------------------------------------------------
__global__ void k_softmax(const float* __restrict__ x) {
    int tid = blockIdx.x * blockDim.x + threadIdx.x;
    if (tid >= G_ * N_) return;
    int g = tid / N_;
    int i = tid - g * N_;
    int lo = g_off[i], hi = g_off[i + 1];
    const float* eb = g_e + g * ETOT;
    const float* xg = x + g * N_;

    float M = -3.0e38f, num = 0.f, den = 0.f;
    for (int s = lo; s < hi; s++) {
        float e  = eb[s];
        float xj = __ldg(&xg[g_src[s]]);
        if (e > M) {
            float sc = __expf(M - e);
            num = fmaf(num, sc, xj);
            den = fmaf(den, sc, 1.f);
            M = e;
        } else {
            float t = __expf(e - M);
            num = fmaf(t, xj, num);
            den += t;
        }
    }
    g_S[tid] = num / den;
}

// ---------------------------------------------------------------------------
// Output broadcast: out[g,n,c] = Wl[c]*S[g,n] + (bl+bias+pos)[t,c]
// ---------------------------------------------------------------------------
__global__ void k_out(const float* __restrict__ Wl, float4* __restrict__ out) {
    int tid = blockIdx.x * blockDim.x + threadIdx.x;
    if (tid >= G_ * N_ * C4_) return;
    int c4   = tid % C4_;
    int rest = tid / C4_;          // g*N_ + n
    int g    = rest / N_;
    int t    = g % T_;

    float  S  = __ldg(&g_S[rest]);
    float4 wl = __ldg(&((const float4*)Wl)[c4]);
    float4 ad = __ldg(&g_add4[t * C4_ + c4]);
    out[tid] = make_float4(fmaf(S, wl.x, ad.x), fmaf(S, wl.y, ad.y),
                           fmaf(S, wl.z, ad.z), fmaf(S, wl.w, ad.w));
}

// ---------------------------------------------------------------------------
extern "C" void kernel_launch(void* const* d_in, const int* in_sizes, int n_in,
                              void* d_out, int out_size) {
    const float* x    = (const float*)d_in[0];
    const int*   EI   = (const int*)  d_in[1];
    const float* Wl   = (const float*)d_in[2];
    const float* bl   = (const float*)d_in[3];
    const float* Wr   = (const float*)d_in[4];
    const float* br   = (const float*)d_in[5];
    const float* att  = (const float*)d_in[6];
    const float* bias = (const float*)d_in[7];

    k_setup  <<<1, 1024>>>(Wl, bl, Wr, br, att, bias);
    k_hist   <<<(ETOT + 255) / 256, 256>>>(EI);
    k_scan   <<<1, 1024>>>();
    k_scatter<<<(ETOT + 255) / 256, 256>>>(EI);
    k_sort   <<<(N_ + 255) / 256, 256>>>(EI);
    k_logits <<<(G_ * ETOT + 255) / 256, 256>>>(x);
    k_softmax<<<(G_ * N_ + 255) / 256, 256>>>(x);
    k_out    <<<(G_ * N_ * C4_ + 255) / 256, 256>>>(Wl, (float4*)d_out);
}

// round 7
// speedup vs baseline: 1.4684x; 1.4684x over previous
#include <cuda_runtime.h>
#include <math.h>

#define B_    32
#define T_    10
#define N_    1000
#define C_    96
#define E_    8000
#define G_    (B_*T_)      // 320
#define ETOT  (E_+N_)      // 9000 (div by 4)
#define C4_   (C_/4)       // 24
#define CP_   (C_/2)       // 48 channel pairs

// ---- device scratch ----
__device__ ulonglong2 g_Pa[CP_];       // {Wl2, Wr2} packed f32x2 per channel pair
__device__ ulonglong2 g_Pb[CP_];       // {K2,  A2 } K=bl+br, A=0.4*att
__device__ float      g_scal[3];       // 0.6*<att,Wl>, 0.6*<att,Wr>, 0.6*<att,bl+br>
__device__ float4     g_add4[T_*C4_];  // bl+bias+pos per (t, c/4)
__device__ int        g_off[N_+1];
__device__ int4       g_sd4[ETOT/2];   // (src,dst) pairs, 2 edges per int4 (16B aligned)
__device__ float      g_e[G_*ETOT];    // logits
__device__ float      g_S[G_*N_];      // softmax-weighted source mean

// ---------------------------------------------------------------------------
// Fused prep: params + dots + pos table + CSR (hist/scan/scatter/sort)
// single block, 1024 threads, everything in smem
// ---------------------------------------------------------------------------
__device__ __forceinline__ int edge_dst(const int* EI, int e) {
    return (e < E_) ? EI[E_ + e] : (e - E_);
}
__device__ __forceinline__ int edge_src(const int* EI, int e) {
    return (e < E_) ? EI[e] : (e - E_);
}

__global__ void k_prep(const int* __restrict__ EI,
                       const float* __restrict__ Wl, const float* __restrict__ bl,
                       const float* __restrict__ Wr, const float* __restrict__ br,
                       const float* __restrict__ att, const float* __restrict__ bias) {
    __shared__ int   sdeg[1024];      // hist / scan workspace
    __shared__ int   soff[N_+1];
    __shared__ int   scnt[N_];
    __shared__ int   stmp[ETOT];      // 36 KB
    __shared__ float sred[32];

    int tid  = threadIdx.x;
    int lane = tid & 31;
    int wid  = tid >> 5;

    // ---- params / packed tables ----
    float d0 = 0.f, d1 = 0.f, d2 = 0.f;
    if (tid < C_) {
        float a = att[tid];
        d0 = a * Wl[tid]; d1 = a * Wr[tid]; d2 = a * (bl[tid] + br[tid]);

        int   pair = tid >> 1;
        float freq = __expf(-(float)(2 * pair) * (logf(10000.f) / (float)C_));
        float badd = bl[tid] + bias[tid];
        float* addf = (float*)g_add4;
        for (int t = 0; t < T_; t++) {
            float arg = (float)t * freq;
            addf[t * C_ + tid] = badd + ((tid & 1) ? cosf(arg) : sinf(arg));
        }
    }
    if (tid < CP_) {
        int c0 = 2 * tid, c1 = 2 * tid + 1;
        float4 pa = make_float4(Wl[c0], Wl[c1], Wr[c0], Wr[c1]);
        float4 pb = make_float4(bl[c0] + br[c0], bl[c1] + br[c1],
                                0.4f * att[c0], 0.4f * att[c1]);
        ((float4*)g_Pa)[tid] = pa;
        ((float4*)g_Pb)[tid] = pb;
    }
    // block-reduce the 3 dots
    float vals[3] = {d0, d1, d2};
    for (int r = 0; r < 3; r++) {
        float v = vals[r];
        #pragma unroll
        for (int o = 16; o; o >>= 1) v += __shfl_down_sync(0xffffffffu, v, o);
        if (lane == 0) sred[wid] = v;
        __syncthreads();
        if (wid == 0) {
            float w = sred[lane];
            #pragma unroll
            for (int o = 16; o; o >>= 1) w += __shfl_down_sync(0xffffffffu, w, o);
            if (lane == 0) g_scal[r] = 0.6f * w;
        }
        __syncthreads();
    }

    // ---- histogram ----
    sdeg[tid] = 0;
    if (tid < N_) scnt[tid] = 0;
    __syncthreads();
    for (int e = tid; e < ETOT; e += 1024)
        atomicAdd(&sdeg[edge_dst(EI, e)], 1);
    __syncthreads();

    // ---- inclusive scan (Hillis-Steele over 1024) ----
    for (int o = 1; o < 1024; o <<= 1) {
        int t = (tid >= o) ? sdeg[tid - o] : 0;
        __syncthreads();
        sdeg[tid] += t;
        __syncthreads();
    }
    if (tid == 0) soff[0] = 0;
    if (tid < N_) soff[tid + 1] = sdeg[tid];
    __syncthreads();
    if (tid <= N_) g_off[tid] = soff[tid];

    // ---- bucket scatter (atomic, order-free) ----
    for (int e = tid; e < ETOT; e += 1024) {
        int d = edge_dst(EI, e);
        stmp[soff[d] + atomicAdd(&scnt[d], 1)] = e;
    }
    __syncthreads();

    // ---- per-node sort by edge id (unique key -> deterministic) + emit ----
    if (tid < N_) {
        int lo = soff[tid], hi = soff[tid + 1];
        for (int a = lo + 1; a < hi; a++) {
            int key = stmp[a];
            int b = a - 1;
            while (b >= lo && stmp[b] > key) { stmp[b + 1] = stmp[b]; b--; }
            stmp[b + 1] = key;
        }
        int2* sd = (int2*)g_sd4;                 // 8B stores to 16B-aligned base
        for (int a = lo; a < hi; a++)
            sd[a] = make_int2(edge_src(EI, stmp[a]), tid);
    }
}

// ---------------------------------------------------------------------------
// Packed f32x2 helpers
// ---------------------------------------------------------------------------
typedef unsigned long long ull;
__device__ __forceinline__ ull fma2(ull a, ull b, ull c) {
    ull d;
    asm("fma.rn.f32x2 %0, %1, %2, %3;" : "=l"(d) : "l"(a), "l"(b), "l"(c));
    return d;
}
__device__ __forceinline__ ull pack2(float v) {
    ull u;
    asm("mov.b64 %0, {%1, %1};" : "=l"(u) : "f"(v));
    return u;
}
__device__ __forceinline__ float sum2(ull u) {
    float lo, hi;
    asm("mov.b64 {%0, %1}, %2;" : "=f"(lo), "=f"(hi) : "l"(u));
    return lo + hi;
}
#define ABS2 0x7FFFFFFF7FFFFFFFULL

// ---------------------------------------------------------------------------
// Logits: 4 edges per thread, packed channel pairs
// e = S0*xj + S1*xi + S2 + sum_c 0.4*att[c]*|xj*Wl[c] + xi*Wr[c] + K[c]|
// ---------------------------------------------------------------------------
__global__ void k_logits(const float* __restrict__ x) {
    __shared__ ulonglong2 sPa[CP_], sPb[CP_];
    __shared__ float      Ssc[3];
    int tl = threadIdx.x;
    if (tl < CP_) { sPa[tl] = g_Pa[tl]; sPb[tl] = g_Pb[tl]; }
    if (tl < 3)   Ssc[tl] = g_scal[tl];
    __syncthreads();

    int t = blockIdx.x * blockDim.x + tl;
    if (t >= G_ * ETOT / 4) return;
    int base = t * 4;                        // global (graph, edge) index
    int g = base / ETOT;                     // ETOT % 4 == 0 -> same g for all 4
    int s = base - g * ETOT;                 // per-graph CSR slot (s % 4 == 0)
    const float* xg = x + g * N_;

    int4 q0 = __ldg(&g_sd4[(s >> 1)]);       // edges s, s+1
    int4 q1 = __ldg(&g_sd4[(s >> 1) + 1]);   // edges s+2, s+3

    float xj[4], xi[4];
    xj[0] = __ldg(&xg[q0.x]); xi[0] = __ldg(&xg[q0.y]);
    xj[1] = __ldg(&xg[q0.z]); xi[1] = __ldg(&xg[q0.w]);
    xj[2] = __ldg(&xg[q1.x]); xi[2] = __ldg(&xg[q1.y]);
    xj[3] = __ldg(&xg[q1.z]); xi[3] = __ldg(&xg[q1.w]);

    ull xj2[4], xi2[4], acc[4];
    #pragma unroll
    for (int e = 0; e < 4; e++) {
        xj2[e] = pack2(xj[e]); xi2[e] = pack2(xi[e]); acc[e] = 0ULL;
    }

    #pragma unroll 8
    for (int c2 = 0; c2 < CP_; c2++) {
        ulonglong2 pa = sPa[c2];    // {Wl2, Wr2}
        ulonglong2 pb = sPb[c2];    // {K2,  A2 }
        #pragma unroll
        for (int e = 0; e < 4; e++) {
            ull z = fma2(xj2[e], pa.x, fma2(xi2[e], pa.y, pb.x));
            z &= ABS2;
            acc[e] = fma2(pb.y, z, acc[e]);
        }
    }

    #pragma unroll
    for (int e = 0; e < 4; e++) {
        float lin = fmaf(Ssc[0], xj[e], fmaf(Ssc[1], xi[e], Ssc[2]));
        g_e[base + e] = lin + sum2(acc[e]);
    }
}

// ---------------------------------------------------------------------------
// Per-node softmax (no max pass: |e| bounded far below exp overflow)
// ---------------------------------------------------------------------------
__global__ void k_softmax(const float* __restrict__ x) {
    int tid = blockIdx.x * blockDim.x + threadIdx.x;
    if (tid >= G_ * N_) return;
    int g = tid / N_;
    int i = tid - g * N_;
    int lo = g_off[i], hi = g_off[i + 1];
    const float* eb = g_e + g * ETOT;
    const float* xg = x + g * N_;
    const int2*  sd = (const int2*)g_sd4;

    float num = 0.f, den = 0.f;
    for (int s = lo; s < hi; s++) {
        float w  = __expf(eb[s]);
        float xj = __ldg(&xg[sd[s].x]);
        num = fmaf(w, xj, num);
        den += w;
    }
    g_S[tid] = num / den;
}

// ---------------------------------------------------------------------------
// Output broadcast: out[g,n,c] = Wl[c]*S[g,n] + (bl+bias+pos)[t,c]
// ---------------------------------------------------------------------------
__global__ void k_out(const float* __restrict__ Wl, float4* __restrict__ out) {
    int tid = blockIdx.x * blockDim.x + threadIdx.x;
    if (tid >= G_ * N_ * C4_) return;
    int c4   = tid % C4_;
    int rest = tid / C4_;          // g*N_ + n
    int g    = rest / N_;
    int t    = g % T_;

    float  S  = __ldg(&g_S[rest]);
    float4 wl = __ldg(&((const float4*)Wl)[c4]);
    float4 ad = __ldg(&g_add4[t * C4_ + c4]);
    out[tid] = make_float4(fmaf(S, wl.x, ad.x), fmaf(S, wl.y, ad.y),
                           fmaf(S, wl.z, ad.z), fmaf(S, wl.w, ad.w));
}

// ---------------------------------------------------------------------------
extern "C" void kernel_launch(void* const* d_in, const int* in_sizes, int n_in,
                              void* d_out, int out_size) {
    const float* x    = (const float*)d_in[0];
    const int*   EI   = (const int*)  d_in[1];
    const float* Wl   = (const float*)d_in[2];
    const float* bl   = (const float*)d_in[3];
    const float* Wr   = (const float*)d_in[4];
    const float* br   = (const float*)d_in[5];
    const float* att  = (const float*)d_in[6];
    const float* bias = (const float*)d_in[7];

    k_prep   <<<1, 1024>>>(EI, Wl, bl, Wr, br, att, bias);
    k_logits <<<(G_ * ETOT / 4 + 255) / 256, 256>>>(x);
    k_softmax<<<(G_ * N_ + 255) / 256, 256>>>(x);
    k_out    <<<(G_ * N_ * C4_ + 255) / 256, 256>>>(Wl, (float4*)d_out);
}